// round 13
// baseline (speedup 1.0000x reference)
#include <cuda_runtime.h>
#include <cuda_fp16.h>
#include <cstdint>

#define T_   16
#define B_   8192
#define DIN  512
#define DH   1024
#define DOUT 256
#define SPLITK 16
#define KSEG (T_*DH/SPLITK)   // 1024

// ---------------- scratch (allocation-free: __device__ globals) -------------
__device__ __half g_xh [(size_t)B_*DIN];          // x fp16
__device__ __half g_w1t[(size_t)T_*DH*DIN];       // W1^T [t][n][k] fp16
__device__ __half g_w2t[(size_t)T_*DH*DH];        // W2^T [t][n][k] fp16
__device__ __half g_w3t[(size_t)DOUT*T_*DH];      // W3^T [n][t*DH+k] fp16
__device__ __half g_h1 [(size_t)B_*T_*DH];        // h1 [b][t][h] fp16
__device__ __half g_h2 [(size_t)B_*T_*DH];        // h2 [b][t][h] fp16
__device__ __half g_part[(size_t)SPLITK*B_*DOUT]; // split-K partials fp16

// ---------------- helpers ---------------------------------------------------
__device__ __forceinline__ uint32_t smem_to_u32(const void* p) {
    uint32_t a;
    asm("{ .reg .u64 t; cvta.to.shared.u64 t, %1; cvt.u32.u64 %0, t; }"
        : "=r"(a) : "l"(p));
    return a;
}
__device__ __forceinline__ void cp16(uint32_t s, const void* g) {
    asm volatile("cp.async.cg.shared.global [%0], [%1], 16;" :: "r"(s), "l"(g));
}
__device__ __forceinline__ void ldsm4(uint32_t* r, uint32_t addr) {
    asm volatile("ldmatrix.sync.aligned.m8n8.x4.shared.b16 {%0,%1,%2,%3}, [%4];"
        : "=r"(r[0]), "=r"(r[1]), "=r"(r[2]), "=r"(r[3]) : "r"(addr));
}
__device__ __forceinline__ void mma16(float* d, const uint32_t* a,
                                      uint32_t b0, uint32_t b1) {
    asm volatile(
        "mma.sync.aligned.m16n8k16.row.col.f32.f16.f16.f32 "
        "{%0,%1,%2,%3}, {%4,%5,%6,%7}, {%8,%9}, {%0,%1,%2,%3};"
        : "+f"(d[0]), "+f"(d[1]), "+f"(d[2]), "+f"(d[3])
        : "r"(a[0]), "r"(a[1]), "r"(a[2]), "r"(a[3]), "r"(b0), "r"(b1));
}

// ---------------- GEMM kernel ----------------------------------------------
// BM=128, BN=128, BK=64 halves. 128 threads = 4 warps as 2(M) x 2(N),
// warp tile 64x64, m16n8k16 fp16 mma. 3-stage cp.async ring, 96KB smem ->
// TWO CTAs PER SM (independent barriers hide each other's sync/fill).
// cp.async issue for the next chunk is SPREAD across the 4 kk-steps
// (4 ops/step) instead of bursting 16 ops into the cold-LDSM window.
constexpr int STAGES      = 3;
constexpr int STAGE_BYTES = (128 + 128) * 128;             // 32768
constexpr int GEMM_SMEM   = STAGES * STAGE_BYTES;          // 98304

// flags: bit0 = add bias, bit1 = relu, bit2 = fp16 output (else fp32)
__global__ void __launch_bounds__(128, 2)
gemm_tc(const __half* __restrict__ A, const __half* __restrict__ B,
        const float* __restrict__ bias, void* __restrict__ Cv,
        int nk, long lda, long ldb, long ldc,
        long a_z, long b_z, long c_z, long bias_z, int flags)
{
    extern __shared__ char smem[];
    const uint32_t sb = smem_to_u32(smem);
    const int tid  = threadIdx.x;
    const int lane = tid & 31;
    const int wid  = tid >> 5;
    const int wm   = wid & 1;        // 2 M warp-rows (64 each)
    const int wn   = wid >> 1;       // 2 N warp-cols (64 each)
    const int z    = blockIdx.z;
    const long m0  = (long)blockIdx.x * 128;
    const long n0  = (long)blockIdx.y * 128;

    const __half* Ag = A + (long)z * a_z + m0 * lda;
    const __half* Bg = B + (long)z * b_z + n0 * ldb;

    // ---- cp.async source pointers / swizzled dest offsets ----
    const __half* asrc[8]; uint32_t adst[8];
    #pragma unroll
    for (int i = 0; i < 8; i++) {
        int idx = tid + i * 128;
        int r = idx >> 3, c = idx & 7;
        asrc[i] = Ag + (long)r * lda + c * 8;
        adst[i] = (uint32_t)(r * 128 + ((c ^ (r & 7)) << 4));
    }
    const __half* bsrc[8]; uint32_t bdst[8];
    #pragma unroll
    for (int i = 0; i < 8; i++) {
        int idx = tid + i * 128;
        int r = idx >> 3, c = idx & 7;
        bsrc[i] = Bg + (long)r * ldb + c * 8;
        bdst[i] = (uint32_t)(16384 + r * 128 + ((c ^ (r & 7)) << 4));
    }
    auto load_chunk = [&](uint32_t base, long koff) {   // full 16-op burst
        #pragma unroll
        for (int i = 0; i < 8; i++) cp16(base + adst[i], asrc[i] + koff);
        #pragma unroll
        for (int i = 0; i < 8; i++) cp16(base + bdst[i], bsrc[i] + koff);
        asm volatile("cp.async.commit_group;" ::: "memory");
    };
    auto load_quarter = [&](uint32_t base, long koff, int q) {  // 4 ops
        #pragma unroll
        for (int i = 0; i < 2; i++) {
            cp16(base + adst[q * 2 + i], asrc[q * 2 + i] + koff);
            cp16(base + bdst[q * 2 + i], bsrc[q * 2 + i] + koff);
        }
    };

    // ---- ldmatrix per-thread base offsets ----
    const int rx   = lane & 7;
    const int a_r  = (lane & 7) + (((lane >> 3) & 1) << 3);
    const int a_cs = (lane >> 4) & 1;           // k-half within k16
    const int b_r  = (lane & 7) + (((lane >> 4) & 1) << 3);
    const int b_cs = (lane >> 3) & 1;
    uint32_t aoff[4], boff[4];
    #pragma unroll
    for (int i = 0; i < 4; i++) aoff[i] = (uint32_t)((wm * 64 + i * 16 + a_r) * 128);
    #pragma unroll
    for (int t = 0; t < 4; t++) boff[t] = (uint32_t)(16384 + (wn * 64 + t * 16 + b_r) * 128);

    float acc[4][8][4];
    #pragma unroll
    for (int i = 0; i < 4; i++)
        #pragma unroll
        for (int j = 0; j < 8; j++)
            #pragma unroll
            for (int e = 0; e < 4; e++) acc[i][j][e] = 0.0f;

    auto ldf = [&](uint32_t stb, int kk, uint32_t af[4][4], uint32_t bf[4][4]) {
        #pragma unroll
        for (int i = 0; i < 4; i++)
            ldsm4(af[i], stb + aoff[i] + (uint32_t)((((kk << 1) + a_cs) ^ rx) << 4));
        #pragma unroll
        for (int t = 0; t < 4; t++)
            ldsm4(bf[t], stb + boff[t] + (uint32_t)((((kk << 1) + b_cs) ^ rx) << 4));
    };

    uint32_t afb[2][4][4], bfb[2][4][4];

    // ---- prologue: chunks 0,1 -> stages 0,1 ----
    load_chunk(sb + 0 * STAGE_BYTES, 0);
    if (nk > 1) load_chunk(sb + 1 * STAGE_BYTES, 64);

    int st_c = 0;                         // stage of chunk k (rotates mod 3)
    for (int k = 0; k < nk; k++) {
        // chunks <= k+1 fully resident (k+2 not yet committed)
        asm volatile("cp.async.wait_group 0;" ::: "memory");
        __syncthreads();                   // readers of stage (k+2)%3 are done

        const int kp = k + 2;
        const bool pf = (kp < nk);
        int st_p = st_c + 2; if (st_p >= STAGES) st_p -= STAGES;
        const uint32_t pbase = sb + st_p * STAGE_BYTES;
        const long pko = (long)kp * 64;

        const uint32_t stc = sb + st_c * STAGE_BYTES;
        if (k == 0) ldf(stc, 0, afb[0], bfb[0]);     // cold start

        int st_n = st_c + 1; if (st_n >= STAGES) st_n -= STAGES;
        #pragma unroll
        for (int kk = 0; kk < 4; kk++) {
            const int cur = kk & 1;
            if (pf) load_quarter(pbase, pko, kk);    // 4 LSU ops per kk-step
            if (kk < 3)           ldf(stc, kk + 1, afb[cur ^ 1], bfb[cur ^ 1]);
            else if (k + 1 < nk)  ldf(sb + st_n * STAGE_BYTES, 0,
                                      afb[cur ^ 1], bfb[cur ^ 1]);
            #pragma unroll
            for (int i = 0; i < 4; i++)
                #pragma unroll
                for (int j = 0; j < 8; j++)
                    mma16(acc[i][j], afb[cur][i],
                          bfb[cur][j >> 1][(j & 1) << 1],
                          bfb[cur][j >> 1][((j & 1) << 1) + 1]);
        }
        if (pf) asm volatile("cp.async.commit_group;" ::: "memory");
        st_c = st_n;
    }

    // ---- epilogue: fused bias / relu, fp16 or fp32 stores ----
    const float* bz = bias + (long)z * bias_z;
    const int g  = lane >> 2;
    const int tg = lane & 3;
    #pragma unroll
    for (int i = 0; i < 4; i++) {
        const long row0 = m0 + wm * 64 + i * 16 + g;
        #pragma unroll
        for (int j = 0; j < 8; j++) {
            const long col = n0 + wn * 64 + j * 8 + tg * 2;
            float2 v0 = make_float2(acc[i][j][0], acc[i][j][1]);
            float2 v1 = make_float2(acc[i][j][2], acc[i][j][3]);
            if (flags & 1) {
                float2 b = *(const float2*)(bz + col);
                v0.x += b.x; v0.y += b.y; v1.x += b.x; v1.y += b.y;
            }
            if (flags & 2) {
                v0.x = fmaxf(v0.x, 0.f); v0.y = fmaxf(v0.y, 0.f);
                v1.x = fmaxf(v1.x, 0.f); v1.y = fmaxf(v1.y, 0.f);
            }
            if (flags & 4) {
                __half* Cz = (__half*)Cv + (long)z * c_z;
                *(__half2*)(Cz + row0 * ldc + col) =
                    __floats2half2_rn(v0.x, v0.y);
                *(__half2*)(Cz + (row0 + 8) * ldc + col) =
                    __floats2half2_rn(v1.x, v1.y);
            } else {
                float* Cz = (float*)Cv + (long)z * c_z;
                *(float2*)(Cz + row0 * ldc + col)       = v0;
                *(float2*)(Cz + (row0 + 8) * ldc + col) = v1;
            }
        }
    }
}

// ---------------- prep / post kernels --------------------------------------
__global__ void cvt_x_h(const float* __restrict__ x, __half* __restrict__ xh) {
    long i = (long)blockIdx.x * 256 + threadIdx.x;     // float4 index
    float4 v = ((const float4*)x)[i];
    ((__half2*)xh)[i * 2 + 0] = __floats2half2_rn(v.x, v.y);
    ((__half2*)xh)[i * 2 + 1] = __floats2half2_rn(v.z, v.w);
}

// in: [z][K][N] fp32 row-major -> out[z*out_z + n*out_ld + z*out_colz + k] fp16
__global__ void transpose_cvt(const float* __restrict__ in, __half* __restrict__ out,
                              int K, int N, long in_z, long out_z,
                              long out_ld, long out_colz)
{
    __shared__ float t[32][33];
    int z = blockIdx.z;
    const float* I = in + (long)z * in_z;
    __half* O = out + (long)z * out_z + (long)z * out_colz;
    int n0 = blockIdx.x * 32, k0 = blockIdx.y * 32;
    int tx = threadIdx.x, ty = threadIdx.y;
    #pragma unroll
    for (int i = 0; i < 32; i += 8)
        t[ty + i][tx] = I[(long)(k0 + ty + i) * N + n0 + tx];
    __syncthreads();
    #pragma unroll
    for (int i = 0; i < 32; i += 8)
        O[(long)(n0 + ty + i) * out_ld + k0 + tx] = __float2half_rn(t[tx][ty + i]);
}

__global__ void reduce_k(const __half* __restrict__ part, const float* __restrict__ b3,
                         float* __restrict__ out)
{
    long i = (long)blockIdx.x * 256 + threadIdx.x;   // group of 4 outputs
    float4 a = make_float4(0.f, 0.f, 0.f, 0.f);
    #pragma unroll
    for (int s = 0; s < SPLITK; s++) {
        long off = ((long)s * B_ * DOUT) / 2 + i * 2;    // half2 index
        float2 f0 = __half22float2(((const __half2*)part)[off]);
        float2 f1 = __half22float2(((const __half2*)part)[off + 1]);
        a.x += f0.x; a.y += f0.y; a.z += f1.x; a.w += f1.y;
    }
    int o4 = (int)(i & (DOUT / 4 - 1));
    float4 bs = make_float4(0.f, 0.f, 0.f, 0.f);
    #pragma unroll
    for (int t = 0; t < T_; t++) {
        float4 b = ((const float4*)b3)[t * (DOUT / 4) + o4];
        bs.x += b.x; bs.y += b.y; bs.z += b.z; bs.w += b.w;
    }
    const float s = 1.0f / T_;
    float4 o;
    o.x = (a.x + bs.x) * s; o.y = (a.y + bs.y) * s;
    o.z = (a.z + bs.z) * s; o.w = (a.w + bs.w) * s;
    ((float4*)out)[i] = o;
}

// ---------------- launcher --------------------------------------------------
extern "C" void kernel_launch(void* const* d_in, const int* in_sizes, int n_in,
                              void* d_out, int out_size)
{
    const float* x  = (const float*)d_in[0];
    const float* W1 = (const float*)d_in[1];
    const float* b1 = (const float*)d_in[2];
    const float* W2 = (const float*)d_in[3];
    const float* b2 = (const float*)d_in[4];
    const float* W3 = (const float*)d_in[5];
    const float* b3 = (const float*)d_in[6];
    float* out = (float*)d_out;

    __half *xh, *w1t, *w2t, *w3t, *h1, *h2, *part;
    cudaGetSymbolAddress((void**)&xh,   g_xh);
    cudaGetSymbolAddress((void**)&w1t,  g_w1t);
    cudaGetSymbolAddress((void**)&w2t,  g_w2t);
    cudaGetSymbolAddress((void**)&w3t,  g_w3t);
    cudaGetSymbolAddress((void**)&h1,   g_h1);
    cudaGetSymbolAddress((void**)&h2,   g_h2);
    cudaGetSymbolAddress((void**)&part, g_part);

    cudaFuncSetAttribute(gemm_tc, cudaFuncAttributeMaxDynamicSharedMemorySize, GEMM_SMEM);

    // prep: x -> fp16; weights -> fp16 transposed [n][k]
    cvt_x_h<<<(B_ * DIN / 4) / 256, 256>>>(x, xh);
    transpose_cvt<<<dim3(DH / 32, DIN / 32, T_), dim3(32, 8)>>>(
        W1, w1t, DIN, DH, (long)DIN * DH, (long)DH * DIN, DIN, 0);
    transpose_cvt<<<dim3(DH / 32, DH / 32, T_), dim3(32, 8)>>>(
        W2, w2t, DH, DH, (long)DH * DH, (long)DH * DH, DH, 0);
    transpose_cvt<<<dim3(DOUT / 32, DH / 32, T_), dim3(32, 8)>>>(
        W3, w3t, DH, DOUT, (long)DH * DOUT, 0, (long)T_ * DH, DH);

    // L1: K=512 -> nk=8
    gemm_tc<<<dim3(B_ / 128, DH / 128, T_), 128, GEMM_SMEM>>>(
        xh, w1t, b1, h1,
        DIN / 64, DIN, DIN, (long)T_ * DH,
        0, (long)DH * DIN, DH, DH, /*flags=*/7);

    // L2: K=1024 -> nk=16
    gemm_tc<<<dim3(B_ / 128, DH / 128, T_), 128, GEMM_SMEM>>>(
        h1, w2t, b2, h2,
        DH / 64, (long)T_ * DH, DH, (long)T_ * DH,
        DH, (long)DH * DH, DH, DH, /*flags=*/7);

    // L3: split-K over K=16384 -> fp16 partials, KSEG=1024 -> nk=16
    gemm_tc<<<dim3(B_ / 128, DOUT / 128, SPLITK), 128, GEMM_SMEM>>>(
        h2, w3t, b3, part,
        KSEG / 64, (long)T_ * DH, (long)T_ * DH, DOUT,
        KSEG, KSEG, (long)B_ * DOUT, 0, /*flags=*/4);

    // reduce partials + mean + summed bias
    reduce_k<<<(B_ * DOUT / 4) / 256, 256>>>(part, b3, out);
}

// round 14
// speedup vs baseline: 1.0448x; 1.0448x over previous
#include <cuda_runtime.h>
#include <cuda_fp16.h>
#include <cstdint>

#define T_   16
#define B_   8192
#define DIN  512
#define DH   1024
#define DOUT 256
#define SPLITK 16
#define KSEG (T_*DH/SPLITK)   // 1024

// ---------------- scratch (allocation-free: __device__ globals) -------------
__device__ __half g_xh [(size_t)B_*DIN];          // x fp16
__device__ __half g_w1t[(size_t)T_*DH*DIN];       // W1^T [t][n][k] fp16
__device__ __half g_w2t[(size_t)T_*DH*DH];        // W2^T [t][n][k] fp16
__device__ __half g_w3t[(size_t)DOUT*T_*DH];      // W3^T [n][t*DH+k] fp16
__device__ __half g_h1 [(size_t)B_*T_*DH];        // h1 [b][t][h] fp16
__device__ __half g_h2 [(size_t)B_*T_*DH];        // h2 [b][t][h] fp16
__device__ __half g_part[(size_t)SPLITK*B_*DOUT]; // split-K partials fp16

// ---------------- helpers ---------------------------------------------------
__device__ __forceinline__ uint32_t smem_to_u32(const void* p) {
    uint32_t a;
    asm("{ .reg .u64 t; cvta.to.shared.u64 t, %1; cvt.u32.u64 %0, t; }"
        : "=r"(a) : "l"(p));
    return a;
}
__device__ __forceinline__ void cp16(uint32_t s, const void* g) {
    asm volatile("cp.async.cg.shared.global [%0], [%1], 16;" :: "r"(s), "l"(g));
}
__device__ __forceinline__ void ldsm4(uint32_t* r, uint32_t addr) {
    asm volatile("ldmatrix.sync.aligned.m8n8.x4.shared.b16 {%0,%1,%2,%3}, [%4];"
        : "=r"(r[0]), "=r"(r[1]), "=r"(r[2]), "=r"(r[3]) : "r"(addr));
}
__device__ __forceinline__ void mma16(float* d, const uint32_t* a,
                                      uint32_t b0, uint32_t b1) {
    asm volatile(
        "mma.sync.aligned.m16n8k16.row.col.f32.f16.f16.f32 "
        "{%0,%1,%2,%3}, {%4,%5,%6,%7}, {%8,%9}, {%0,%1,%2,%3};"
        : "+f"(d[0]), "+f"(d[1]), "+f"(d[2]), "+f"(d[3])
        : "r"(a[0]), "r"(a[1]), "r"(a[2]), "r"(a[3]), "r"(b0), "r"(b1));
}

// ---------------- GEMM kernel ----------------------------------------------
// BM=128, BN=128, BK=64 halves. 128 threads = 4 warps as 2(M) x 2(N),
// warp tile 64x64 (the proven LDSM:MMA ratio), m16n8k16 fp16 mma.
// 3-stage cp.async ring, 96KB smem -> TWO CTAs PER SM: independent barriers
// mean one CTA's sync/fill/epilogue is covered by the other's MMA stream.
// (R9 structure exactly: burst chunk load after the barrier — the spread-LSU
// variant of R10/R13 measured SLOWER.)
constexpr int STAGES      = 3;
constexpr int STAGE_BYTES = (128 + 128) * 128;             // 32768
constexpr int GEMM_SMEM   = STAGES * STAGE_BYTES;          // 98304

// flags: bit0 = add bias, bit1 = relu, bit2 = fp16 output (else fp32)
__global__ void __launch_bounds__(128, 2)
gemm_tc(const __half* __restrict__ A, const __half* __restrict__ B,
        const float* __restrict__ bias, void* __restrict__ Cv,
        int nk, long lda, long ldb, long ldc,
        long a_z, long b_z, long c_z, long bias_z, int flags)
{
    extern __shared__ char smem[];
    const uint32_t sb = smem_to_u32(smem);
    const int tid  = threadIdx.x;
    const int lane = tid & 31;
    const int wid  = tid >> 5;
    const int wm   = wid & 1;        // 2 M warp-rows (64 each)
    const int wn   = wid >> 1;       // 2 N warp-cols (64 each)
    const int z    = blockIdx.z;
    const long m0  = (long)blockIdx.x * 128;
    const long n0  = (long)blockIdx.y * 128;

    const __half* Ag = A + (long)z * a_z + m0 * lda;
    const __half* Bg = B + (long)z * b_z + n0 * ldb;

    // ---- cp.async source pointers / swizzled dest offsets ----
    const __half* asrc[8]; uint32_t adst[8];
    #pragma unroll
    for (int i = 0; i < 8; i++) {
        int idx = tid + i * 128;
        int r = idx >> 3, c = idx & 7;
        asrc[i] = Ag + (long)r * lda + c * 8;
        adst[i] = (uint32_t)(r * 128 + ((c ^ (r & 7)) << 4));
    }
    const __half* bsrc[8]; uint32_t bdst[8];
    #pragma unroll
    for (int i = 0; i < 8; i++) {
        int idx = tid + i * 128;
        int r = idx >> 3, c = idx & 7;
        bsrc[i] = Bg + (long)r * ldb + c * 8;
        bdst[i] = (uint32_t)(16384 + r * 128 + ((c ^ (r & 7)) << 4));
    }
    auto load_chunk = [&](uint32_t base, long koff) {
        #pragma unroll
        for (int i = 0; i < 8; i++) cp16(base + adst[i], asrc[i] + koff);
        #pragma unroll
        for (int i = 0; i < 8; i++) cp16(base + bdst[i], bsrc[i] + koff);
        asm volatile("cp.async.commit_group;" ::: "memory");
    };

    // ---- ldmatrix per-thread base offsets ----
    const int rx   = lane & 7;
    const int a_r  = (lane & 7) + (((lane >> 3) & 1) << 3);
    const int a_cs = (lane >> 4) & 1;           // k-half within k16
    const int b_r  = (lane & 7) + (((lane >> 4) & 1) << 3);
    const int b_cs = (lane >> 3) & 1;
    uint32_t aoff[4], boff[4];
    #pragma unroll
    for (int i = 0; i < 4; i++) aoff[i] = (uint32_t)((wm * 64 + i * 16 + a_r) * 128);
    #pragma unroll
    for (int t = 0; t < 4; t++) boff[t] = (uint32_t)(16384 + (wn * 64 + t * 16 + b_r) * 128);

    float acc[4][8][4];
    #pragma unroll
    for (int i = 0; i < 4; i++)
        #pragma unroll
        for (int j = 0; j < 8; j++)
            #pragma unroll
            for (int e = 0; e < 4; e++) acc[i][j][e] = 0.0f;

    auto ldf = [&](uint32_t stb, int kk, uint32_t af[4][4], uint32_t bf[4][4]) {
        #pragma unroll
        for (int i = 0; i < 4; i++)
            ldsm4(af[i], stb + aoff[i] + (uint32_t)((((kk << 1) + a_cs) ^ rx) << 4));
        #pragma unroll
        for (int t = 0; t < 4; t++)
            ldsm4(bf[t], stb + boff[t] + (uint32_t)((((kk << 1) + b_cs) ^ rx) << 4));
    };

    uint32_t afb[2][4][4], bfb[2][4][4];

    // ---- prologue: chunks 0,1 -> stages 0,1 ----
    load_chunk(sb + 0 * STAGE_BYTES, 0);
    if (nk > 1) load_chunk(sb + 1 * STAGE_BYTES, 64);

    int st_c = 0;                         // stage of chunk k (rotates mod 3)
    for (int k = 0; k < nk; k++) {
        // chunks <= k+1 fully resident (k+2 not yet committed)
        asm volatile("cp.async.wait_group 0;" ::: "memory");
        __syncthreads();                   // readers of stage (k+2)%3 are done

        const int kp = k + 2;
        int st_p = st_c + 2; if (st_p >= STAGES) st_p -= STAGES;
        if (kp < nk) load_chunk(sb + st_p * STAGE_BYTES, (long)kp * 64);

        const uint32_t stc = sb + st_c * STAGE_BYTES;
        if (k == 0) ldf(stc, 0, afb[0], bfb[0]);     // cold start

        int st_n = st_c + 1; if (st_n >= STAGES) st_n -= STAGES;
        #pragma unroll
        for (int kk = 0; kk < 4; kk++) {
            const int cur = kk & 1;
            if (kk < 3)           ldf(stc, kk + 1, afb[cur ^ 1], bfb[cur ^ 1]);
            else if (k + 1 < nk)  ldf(sb + st_n * STAGE_BYTES, 0,
                                      afb[cur ^ 1], bfb[cur ^ 1]);
            #pragma unroll
            for (int i = 0; i < 4; i++)
                #pragma unroll
                for (int j = 0; j < 8; j++)
                    mma16(acc[i][j], afb[cur][i],
                          bfb[cur][j >> 1][(j & 1) << 1],
                          bfb[cur][j >> 1][((j & 1) << 1) + 1]);
        }
        st_c = st_n;
    }

    // ---- epilogue: fused bias / relu, fp16 or fp32 stores ----
    const float* bz = bias + (long)z * bias_z;
    const int g  = lane >> 2;
    const int tg = lane & 3;
    #pragma unroll
    for (int i = 0; i < 4; i++) {
        const long row0 = m0 + wm * 64 + i * 16 + g;
        #pragma unroll
        for (int j = 0; j < 8; j++) {
            const long col = n0 + wn * 64 + j * 8 + tg * 2;
            float2 v0 = make_float2(acc[i][j][0], acc[i][j][1]);
            float2 v1 = make_float2(acc[i][j][2], acc[i][j][3]);
            if (flags & 1) {
                float2 b = *(const float2*)(bz + col);
                v0.x += b.x; v0.y += b.y; v1.x += b.x; v1.y += b.y;
            }
            if (flags & 2) {
                v0.x = fmaxf(v0.x, 0.f); v0.y = fmaxf(v0.y, 0.f);
                v1.x = fmaxf(v1.x, 0.f); v1.y = fmaxf(v1.y, 0.f);
            }
            if (flags & 4) {
                __half* Cz = (__half*)Cv + (long)z * c_z;
                *(__half2*)(Cz + row0 * ldc + col) =
                    __floats2half2_rn(v0.x, v0.y);
                *(__half2*)(Cz + (row0 + 8) * ldc + col) =
                    __floats2half2_rn(v1.x, v1.y);
            } else {
                float* Cz = (float*)Cv + (long)z * c_z;
                *(float2*)(Cz + row0 * ldc + col)       = v0;
                *(float2*)(Cz + (row0 + 8) * ldc + col) = v1;
            }
        }
    }
}

// ---------------- prep / post kernels --------------------------------------
__global__ void cvt_x_h(const float* __restrict__ x, __half* __restrict__ xh) {
    long i = (long)blockIdx.x * 256 + threadIdx.x;     // float4 index
    float4 v = ((const float4*)x)[i];
    ((__half2*)xh)[i * 2 + 0] = __floats2half2_rn(v.x, v.y);
    ((__half2*)xh)[i * 2 + 1] = __floats2half2_rn(v.z, v.w);
}

// in: [z][K][N] fp32 row-major -> out[z*out_z + n*out_ld + z*out_colz + k] fp16
__global__ void transpose_cvt(const float* __restrict__ in, __half* __restrict__ out,
                              int K, int N, long in_z, long out_z,
                              long out_ld, long out_colz)
{
    __shared__ float t[32][33];
    int z = blockIdx.z;
    const float* I = in + (long)z * in_z;
    __half* O = out + (long)z * out_z + (long)z * out_colz;
    int n0 = blockIdx.x * 32, k0 = blockIdx.y * 32;
    int tx = threadIdx.x, ty = threadIdx.y;
    #pragma unroll
    for (int i = 0; i < 32; i += 8)
        t[ty + i][tx] = I[(long)(k0 + ty + i) * N + n0 + tx];
    __syncthreads();
    #pragma unroll
    for (int i = 0; i < 32; i += 8)
        O[(long)(n0 + ty + i) * out_ld + k0 + tx] = __float2half_rn(t[tx][ty + i]);
}

__global__ void reduce_k(const __half* __restrict__ part, const float* __restrict__ b3,
                         float* __restrict__ out)
{
    long i = (long)blockIdx.x * 256 + threadIdx.x;   // group of 4 outputs
    float4 a = make_float4(0.f, 0.f, 0.f, 0.f);
    #pragma unroll
    for (int s = 0; s < SPLITK; s++) {
        long off = ((long)s * B_ * DOUT) / 2 + i * 2;    // half2 index
        float2 f0 = __half22float2(((const __half2*)part)[off]);
        float2 f1 = __half22float2(((const __half2*)part)[off + 1]);
        a.x += f0.x; a.y += f0.y; a.z += f1.x; a.w += f1.y;
    }
    int o4 = (int)(i & (DOUT / 4 - 1));
    float4 bs = make_float4(0.f, 0.f, 0.f, 0.f);
    #pragma unroll
    for (int t = 0; t < T_; t++) {
        float4 b = ((const float4*)b3)[t * (DOUT / 4) + o4];
        bs.x += b.x; bs.y += b.y; bs.z += b.z; bs.w += b.w;
    }
    const float s = 1.0f / T_;
    float4 o;
    o.x = (a.x + bs.x) * s; o.y = (a.y + bs.y) * s;
    o.z = (a.z + bs.z) * s; o.w = (a.w + bs.w) * s;
    ((float4*)out)[i] = o;
}

// ---------------- launcher --------------------------------------------------
extern "C" void kernel_launch(void* const* d_in, const int* in_sizes, int n_in,
                              void* d_out, int out_size)
{
    const float* x  = (const float*)d_in[0];
    const float* W1 = (const float*)d_in[1];
    const float* b1 = (const float*)d_in[2];
    const float* W2 = (const float*)d_in[3];
    const float* b2 = (const float*)d_in[4];
    const float* W3 = (const float*)d_in[5];
    const float* b3 = (const float*)d_in[6];
    float* out = (float*)d_out;

    __half *xh, *w1t, *w2t, *w3t, *h1, *h2, *part;
    cudaGetSymbolAddress((void**)&xh,   g_xh);
    cudaGetSymbolAddress((void**)&w1t,  g_w1t);
    cudaGetSymbolAddress((void**)&w2t,  g_w2t);
    cudaGetSymbolAddress((void**)&w3t,  g_w3t);
    cudaGetSymbolAddress((void**)&h1,   g_h1);
    cudaGetSymbolAddress((void**)&h2,   g_h2);
    cudaGetSymbolAddress((void**)&part, g_part);

    cudaFuncSetAttribute(gemm_tc, cudaFuncAttributeMaxDynamicSharedMemorySize, GEMM_SMEM);

    // prep: x -> fp16; weights -> fp16 transposed [n][k]
    cvt_x_h<<<(B_ * DIN / 4) / 256, 256>>>(x, xh);
    transpose_cvt<<<dim3(DH / 32, DIN / 32, T_), dim3(32, 8)>>>(
        W1, w1t, DIN, DH, (long)DIN * DH, (long)DH * DIN, DIN, 0);
    transpose_cvt<<<dim3(DH / 32, DH / 32, T_), dim3(32, 8)>>>(
        W2, w2t, DH, DH, (long)DH * DH, (long)DH * DH, DH, 0);
    transpose_cvt<<<dim3(DOUT / 32, DH / 32, T_), dim3(32, 8)>>>(
        W3, w3t, DH, DOUT, (long)DH * DOUT, 0, (long)T_ * DH, DH);

    // L1: K=512 -> nk=8
    gemm_tc<<<dim3(B_ / 128, DH / 128, T_), 128, GEMM_SMEM>>>(
        xh, w1t, b1, h1,
        DIN / 64, DIN, DIN, (long)T_ * DH,
        0, (long)DH * DIN, DH, DH, /*flags=*/7);

    // L2: K=1024 -> nk=16
    gemm_tc<<<dim3(B_ / 128, DH / 128, T_), 128, GEMM_SMEM>>>(
        h1, w2t, b2, h2,
        DH / 64, (long)T_ * DH, DH, (long)T_ * DH,
        DH, (long)DH * DH, DH, DH, /*flags=*/7);

    // L3: split-K over K=16384 -> fp16 partials, KSEG=1024 -> nk=16
    gemm_tc<<<dim3(B_ / 128, DOUT / 128, SPLITK), 128, GEMM_SMEM>>>(
        h2, w3t, b3, part,
        KSEG / 64, (long)T_ * DH, (long)T_ * DH, DOUT,
        KSEG, KSEG, (long)B_ * DOUT, 0, /*flags=*/4);

    // reduce partials + mean + summed bias
    reduce_k<<<(B_ * DOUT / 4) / 256, 256>>>(part, b3, out);
}

// round 16
// speedup vs baseline: 1.0577x; 1.0124x over previous
#include <cuda_runtime.h>
#include <cuda_fp16.h>
#include <cstdint>

#define T_   16
#define B_   8192
#define DIN  512
#define DH   1024
#define DOUT 256
#define SPLITK 16
#define KSEG (T_*DH/SPLITK)   // 1024

// ---------------- scratch (allocation-free: __device__ globals) -------------
__device__ __half g_xh [(size_t)B_*DIN];          // x fp16
__device__ __half g_w1t[(size_t)T_*DH*DIN];       // W1^T [t][n][k] fp16
__device__ __half g_w2t[(size_t)T_*DH*DH];        // W2^T [t][n][k] fp16
__device__ __half g_w3t[(size_t)DOUT*T_*DH];      // W3^T [n][t*DH+k] fp16
__device__ __half g_h1 [(size_t)B_*T_*DH];        // h1 [b][t][h] fp16
__device__ __half g_h2 [(size_t)B_*T_*DH];        // h2 [b][t][h] fp16
__device__ __half g_part[(size_t)SPLITK*B_*DOUT]; // split-K partials fp16

// ---------------- helpers ---------------------------------------------------
__device__ __forceinline__ uint32_t smem_to_u32(const void* p) {
    uint32_t a;
    asm("{ .reg .u64 t; cvta.to.shared.u64 t, %1; cvt.u32.u64 %0, t; }"
        : "=r"(a) : "l"(p));
    return a;
}
__device__ __forceinline__ void cp16(uint32_t s, const void* g) {
    asm volatile("cp.async.cg.shared.global [%0], [%1], 16;" :: "r"(s), "l"(g));
}
__device__ __forceinline__ void ldsm4(uint32_t* r, uint32_t addr) {
    asm volatile("ldmatrix.sync.aligned.m8n8.x4.shared.b16 {%0,%1,%2,%3}, [%4];"
        : "=r"(r[0]), "=r"(r[1]), "=r"(r[2]), "=r"(r[3]) : "r"(addr));
}
__device__ __forceinline__ void mma16(float* d, const uint32_t* a,
                                      uint32_t b0, uint32_t b1) {
    asm volatile(
        "mma.sync.aligned.m16n8k16.row.col.f32.f16.f16.f32 "
        "{%0,%1,%2,%3}, {%4,%5,%6,%7}, {%8,%9}, {%0,%1,%2,%3};"
        : "+f"(d[0]), "+f"(d[1]), "+f"(d[2]), "+f"(d[3])
        : "r"(a[0]), "r"(a[1]), "r"(a[2]), "r"(a[3]), "r"(b0), "r"(b1));
}

// ---------------- GEMM kernel (UNCHANGED from the 1166us R14 version) -------
// BM=128, BN=128, BK=64 halves. 128 threads = 4 warps as 2(M) x 2(N),
// warp tile 64x64, m16n8k16 fp16 mma. 3-stage cp.async ring, 96KB smem ->
// TWO CTAs PER SM (independent barriers hide each other's sync/fill).
constexpr int STAGES      = 3;
constexpr int STAGE_BYTES = (128 + 128) * 128;             // 32768
constexpr int GEMM_SMEM   = STAGES * STAGE_BYTES;          // 98304

// flags: bit0 = add bias, bit1 = relu, bit2 = fp16 output (else fp32)
__global__ void __launch_bounds__(128, 2)
gemm_tc(const __half* __restrict__ A, const __half* __restrict__ B,
        const float* __restrict__ bias, void* __restrict__ Cv,
        int nk, long lda, long ldb, long ldc,
        long a_z, long b_z, long c_z, long bias_z, int flags)
{
    extern __shared__ char smem[];
    const uint32_t sb = smem_to_u32(smem);
    const int tid  = threadIdx.x;
    const int lane = tid & 31;
    const int wid  = tid >> 5;
    const int wm   = wid & 1;        // 2 M warp-rows (64 each)
    const int wn   = wid >> 1;       // 2 N warp-cols (64 each)
    const int z    = blockIdx.z;
    const long m0  = (long)blockIdx.x * 128;
    const long n0  = (long)blockIdx.y * 128;

    const __half* Ag = A + (long)z * a_z + m0 * lda;
    const __half* Bg = B + (long)z * b_z + n0 * ldb;

    const __half* asrc[8]; uint32_t adst[8];
    #pragma unroll
    for (int i = 0; i < 8; i++) {
        int idx = tid + i * 128;
        int r = idx >> 3, c = idx & 7;
        asrc[i] = Ag + (long)r * lda + c * 8;
        adst[i] = (uint32_t)(r * 128 + ((c ^ (r & 7)) << 4));
    }
    const __half* bsrc[8]; uint32_t bdst[8];
    #pragma unroll
    for (int i = 0; i < 8; i++) {
        int idx = tid + i * 128;
        int r = idx >> 3, c = idx & 7;
        bsrc[i] = Bg + (long)r * ldb + c * 8;
        bdst[i] = (uint32_t)(16384 + r * 128 + ((c ^ (r & 7)) << 4));
    }
    auto load_chunk = [&](uint32_t base, long koff) {
        #pragma unroll
        for (int i = 0; i < 8; i++) cp16(base + adst[i], asrc[i] + koff);
        #pragma unroll
        for (int i = 0; i < 8; i++) cp16(base + bdst[i], bsrc[i] + koff);
        asm volatile("cp.async.commit_group;" ::: "memory");
    };

    const int rx   = lane & 7;
    const int a_r  = (lane & 7) + (((lane >> 3) & 1) << 3);
    const int a_cs = (lane >> 4) & 1;
    const int b_r  = (lane & 7) + (((lane >> 4) & 1) << 3);
    const int b_cs = (lane >> 3) & 1;
    uint32_t aoff[4], boff[4];
    #pragma unroll
    for (int i = 0; i < 4; i++) aoff[i] = (uint32_t)((wm * 64 + i * 16 + a_r) * 128);
    #pragma unroll
    for (int t = 0; t < 4; t++) boff[t] = (uint32_t)(16384 + (wn * 64 + t * 16 + b_r) * 128);

    float acc[4][8][4];
    #pragma unroll
    for (int i = 0; i < 4; i++)
        #pragma unroll
        for (int j = 0; j < 8; j++)
            #pragma unroll
            for (int e = 0; e < 4; e++) acc[i][j][e] = 0.0f;

    auto ldf = [&](uint32_t stb, int kk, uint32_t af[4][4], uint32_t bf[4][4]) {
        #pragma unroll
        for (int i = 0; i < 4; i++)
            ldsm4(af[i], stb + aoff[i] + (uint32_t)((((kk << 1) + a_cs) ^ rx) << 4));
        #pragma unroll
        for (int t = 0; t < 4; t++)
            ldsm4(bf[t], stb + boff[t] + (uint32_t)((((kk << 1) + b_cs) ^ rx) << 4));
    };

    uint32_t afb[2][4][4], bfb[2][4][4];

    load_chunk(sb + 0 * STAGE_BYTES, 0);
    if (nk > 1) load_chunk(sb + 1 * STAGE_BYTES, 64);

    int st_c = 0;
    for (int k = 0; k < nk; k++) {
        asm volatile("cp.async.wait_group 0;" ::: "memory");
        __syncthreads();

        const int kp = k + 2;
        int st_p = st_c + 2; if (st_p >= STAGES) st_p -= STAGES;
        if (kp < nk) load_chunk(sb + st_p * STAGE_BYTES, (long)kp * 64);

        const uint32_t stc = sb + st_c * STAGE_BYTES;
        if (k == 0) ldf(stc, 0, afb[0], bfb[0]);

        int st_n = st_c + 1; if (st_n >= STAGES) st_n -= STAGES;
        #pragma unroll
        for (int kk = 0; kk < 4; kk++) {
            const int cur = kk & 1;
            if (kk < 3)           ldf(stc, kk + 1, afb[cur ^ 1], bfb[cur ^ 1]);
            else if (k + 1 < nk)  ldf(sb + st_n * STAGE_BYTES, 0,
                                      afb[cur ^ 1], bfb[cur ^ 1]);
            #pragma unroll
            for (int i = 0; i < 4; i++)
                #pragma unroll
                for (int j = 0; j < 8; j++)
                    mma16(acc[i][j], afb[cur][i],
                          bfb[cur][j >> 1][(j & 1) << 1],
                          bfb[cur][j >> 1][((j & 1) << 1) + 1]);
        }
        st_c = st_n;
    }

    const float* bz = bias + (long)z * bias_z;
    const int g  = lane >> 2;
    const int tg = lane & 3;
    #pragma unroll
    for (int i = 0; i < 4; i++) {
        const long row0 = m0 + wm * 64 + i * 16 + g;
        #pragma unroll
        for (int j = 0; j < 8; j++) {
            const long col = n0 + wn * 64 + j * 8 + tg * 2;
            float2 v0 = make_float2(acc[i][j][0], acc[i][j][1]);
            float2 v1 = make_float2(acc[i][j][2], acc[i][j][3]);
            if (flags & 1) {
                float2 b = *(const float2*)(bz + col);
                v0.x += b.x; v0.y += b.y; v1.x += b.x; v1.y += b.y;
            }
            if (flags & 2) {
                v0.x = fmaxf(v0.x, 0.f); v0.y = fmaxf(v0.y, 0.f);
                v1.x = fmaxf(v1.x, 0.f); v1.y = fmaxf(v1.y, 0.f);
            }
            if (flags & 4) {
                __half* Cz = (__half*)Cv + (long)z * c_z;
                *(__half2*)(Cz + row0 * ldc + col) =
                    __floats2half2_rn(v0.x, v0.y);
                *(__half2*)(Cz + (row0 + 8) * ldc + col) =
                    __floats2half2_rn(v1.x, v1.y);
            } else {
                float* Cz = (float*)Cv + (long)z * c_z;
                *(float2*)(Cz + row0 * ldc + col)       = v0;
                *(float2*)(Cz + (row0 + 8) * ldc + col) = v1;
            }
        }
    }
}

// ---------------- fused prep kernel -----------------------------------------
// One launch: x->fp16 copy + all 3 weight transposes ([K,N]->[N,K] fp16).
// 32(n) x 64(k) tile staged through smem: loads are 128B-coalesced, stores are
// half2-wide 128B-per-warp. Smem reads use two SCALAR float loads (the float2
// variant faulted: row stride 65 floats makes &sm[r][2tx] only 4B-aligned).
__device__ __forceinline__ void transpose_tile64(
    const float* __restrict__ in, __half* __restrict__ out,
    int Nsrc, long out_ld, int n0, int k0, float sm[32][65], int tid)
{
    const int tx = tid & 31, ty = tid >> 5;       // (32, 8)
    #pragma unroll
    for (int kk = 0; kk < 8; kk++)                 // load 64 k-rows x 32 n-cols
        sm[tx][kk * 8 + ty] = in[(long)(k0 + kk * 8 + ty) * Nsrc + n0 + tx];
    __syncthreads();
    #pragma unroll
    for (int nn = 0; nn < 4; nn++) {               // store 32 n-rows x 64 k
        int n = n0 + nn * 8 + ty;
        float f0 = sm[nn * 8 + ty][2 * tx];
        float f1 = sm[nn * 8 + ty][2 * tx + 1];
        ((__half2*)out)[((long)n * out_ld + k0) / 2 + tx] =
            __floats2half2_rn(f0, f1);
    }
}

__global__ void __launch_bounds__(256)
prep_all(const float* __restrict__ x,
         const float* __restrict__ W1, const float* __restrict__ W2,
         const float* __restrict__ W3,
         __half* __restrict__ xh, __half* __restrict__ w1t,
         __half* __restrict__ w2t, __half* __restrict__ w3t)
{
    __shared__ float sm[32][65];
    const int b = blockIdx.x;
    const int tid = threadIdx.x;
    if (b < 4096) {                       // W1: [t][k=512][n=1024] -> [t][n][k]
        int t = b >> 8, rem = b & 255;    // 32 ntiles x 8 ktiles
        int nt = rem & 31, kt = rem >> 5;
        transpose_tile64(W1 + (long)t * DIN * DH, w1t + (long)t * DH * DIN,
                         DH, DIN, nt * 32, kt * 64, sm, tid);
    } else if (b < 12288) {               // W2: [t][k=1024][n=1024] -> [t][n][k]
        int id = b - 4096;
        int t = id >> 9, rem = id & 511;  // 32 ntiles x 16 ktiles
        int nt = rem & 31, kt = rem >> 5;
        transpose_tile64(W2 + (long)t * DH * DH, w2t + (long)t * DH * DH,
                         DH, DH, nt * 32, kt * 64, sm, tid);
    } else if (b < 14336) {               // W3: [t][k=1024][n=256] -> [n][t*DH+k]
        int id = b - 12288;
        int t = id >> 7, rem = id & 127;  // 8 ntiles x 16 ktiles
        int nt = rem & 7, kt = rem >> 3;
        transpose_tile64(W3 + (long)t * DH * DOUT, w3t + (long)t * DH,
                         DOUT, (long)T_ * DH, nt * 32, kt * 64, sm, tid);
    } else {                              // x -> fp16 (float4-wide)
        long i = (long)(b - 14336) * 256 + tid;
        float4 v = ((const float4*)x)[i];
        ((__half2*)xh)[i * 2 + 0] = __floats2half2_rn(v.x, v.y);
        ((__half2*)xh)[i * 2 + 1] = __floats2half2_rn(v.z, v.w);
    }
}

// ---------------- reduce kernel ---------------------------------------------
__global__ void reduce_k(const __half* __restrict__ part, const float* __restrict__ b3,
                         float* __restrict__ out)
{
    long i = (long)blockIdx.x * 256 + threadIdx.x;   // group of 4 outputs
    float4 a = make_float4(0.f, 0.f, 0.f, 0.f);
    #pragma unroll
    for (int s = 0; s < SPLITK; s++) {
        long off = ((long)s * B_ * DOUT) / 2 + i * 2;    // half2 index
        float2 f0 = __half22float2(((const __half2*)part)[off]);
        float2 f1 = __half22float2(((const __half2*)part)[off + 1]);
        a.x += f0.x; a.y += f0.y; a.z += f1.x; a.w += f1.y;
    }
    int o4 = (int)(i & (DOUT / 4 - 1));
    float4 bs = make_float4(0.f, 0.f, 0.f, 0.f);
    #pragma unroll
    for (int t = 0; t < T_; t++) {
        float4 b = ((const float4*)b3)[t * (DOUT / 4) + o4];
        bs.x += b.x; bs.y += b.y; bs.z += b.z; bs.w += b.w;
    }
    const float s = 1.0f / T_;
    float4 o;
    o.x = (a.x + bs.x) * s; o.y = (a.y + bs.y) * s;
    o.z = (a.z + bs.z) * s; o.w = (a.w + bs.w) * s;
    ((float4*)out)[i] = o;
}

// ---------------- launcher --------------------------------------------------
extern "C" void kernel_launch(void* const* d_in, const int* in_sizes, int n_in,
                              void* d_out, int out_size)
{
    const float* x  = (const float*)d_in[0];
    const float* W1 = (const float*)d_in[1];
    const float* b1 = (const float*)d_in[2];
    const float* W2 = (const float*)d_in[3];
    const float* b2 = (const float*)d_in[4];
    const float* W3 = (const float*)d_in[5];
    const float* b3 = (const float*)d_in[6];
    float* out = (float*)d_out;

    __half *xh, *w1t, *w2t, *w3t, *h1, *h2, *part;
    cudaGetSymbolAddress((void**)&xh,   g_xh);
    cudaGetSymbolAddress((void**)&w1t,  g_w1t);
    cudaGetSymbolAddress((void**)&w2t,  g_w2t);
    cudaGetSymbolAddress((void**)&w3t,  g_w3t);
    cudaGetSymbolAddress((void**)&h1,   g_h1);
    cudaGetSymbolAddress((void**)&h2,   g_h2);
    cudaGetSymbolAddress((void**)&part, g_part);

    cudaFuncSetAttribute(gemm_tc, cudaFuncAttributeMaxDynamicSharedMemorySize, GEMM_SMEM);

    // fused prep: x -> fp16; all weights -> fp16 transposed [n][k]
    prep_all<<<18432, 256>>>(x, W1, W2, W3, xh, w1t, w2t, w3t);

    // L1: K=512 -> nk=8
    gemm_tc<<<dim3(B_ / 128, DH / 128, T_), 128, GEMM_SMEM>>>(
        xh, w1t, b1, h1,
        DIN / 64, DIN, DIN, (long)T_ * DH,
        0, (long)DH * DIN, DH, DH, /*flags=*/7);

    // L2: K=1024 -> nk=16
    gemm_tc<<<dim3(B_ / 128, DH / 128, T_), 128, GEMM_SMEM>>>(
        h1, w2t, b2, h2,
        DH / 64, (long)T_ * DH, DH, (long)T_ * DH,
        DH, (long)DH * DH, DH, DH, /*flags=*/7);

    // L3: split-K over K=16384 -> fp16 partials, KSEG=1024 -> nk=16
    gemm_tc<<<dim3(B_ / 128, DOUT / 128, SPLITK), 128, GEMM_SMEM>>>(
        h2, w3t, b3, part,
        KSEG / 64, (long)T_ * DH, (long)T_ * DH, DOUT,
        KSEG, KSEG, (long)B_ * DOUT, 0, /*flags=*/4);

    // reduce partials + mean + summed bias
    reduce_k<<<(B_ * DOUT / 4) / 256, 256>>>(part, b3, out);
}